// round 1
// baseline (speedup 1.0000x reference)
#include <cuda_runtime.h>
#include <cuda_bf16.h>
#include <math.h>

// ---------------- problem constants ----------------
#define Bsz   64
#define IMGSZ 384
#define PATCH 16
#define CH    192
#define KNN   5
#define HGRID 24
#define NNODE 576            // per image
#define BN    (Bsz * NNODE)  // 36864 global nodes
#define EDG   (BN * KNN)     // 184320 edges
#define HID   768
#define PHID  1024

// ---------------- scratch (no allocations allowed) ----------------
__device__ float g_wt  [768 * 192];        // transposed stem weight [K=768][N=192]
__device__ float g_nf  [(size_t)BN * CH];  // node features
__device__ float g_sq  [BN];
__device__ float g_d2  [(size_t)Bsz * NNODE * NNODE];
__device__ int   g_idx [BN * KNN];
__device__ float g_P   [(size_t)BN * CH];
__device__ float g_Q   [(size_t)BN * CH];
__device__ float g_att [EDG];
__device__ float g_h   [(size_t)BN * CH];
__device__ float g_hm  [(size_t)BN * CH];
__device__ float g_u   [(size_t)BN * HID];
__device__ float g_t   [(size_t)BN * CH];
__device__ float g_g   [Bsz * CH];
__device__ float g_p   [Bsz * PHID];

// ---------------- helpers ----------------
__device__ __forceinline__ float gelu_exact(float v) {
    return 0.5f * v * (1.0f + erff(v * 0.70710678118654752f));
}

// ---------------- generic tiled SGEMM ----------------
// C[M,N] = A[M,K] @ B[K,N], epilogue variants.
// Requirements: M%64==0, N%64==0, K%16==0, pointers 16B aligned.
#define BM 64
#define BNT 64
#define BKT 16

// EPI: 0=none, 1=+bias, 2=relu(+bias), 3=gelu((x+bias)*g+be), 4=res + (x+bias)*g+be
template <int EPI>
__global__ __launch_bounds__(256) void sgemm_kernel(
    const float* __restrict__ A, const float* __restrict__ B, float* __restrict__ C,
    int M, int N, int K,
    const float* __restrict__ bias, const float* __restrict__ gam,
    const float* __restrict__ bet,  const float* __restrict__ res)
{
    __shared__ float As[BKT][BM];
    __shared__ float Bs[BKT][BNT];
    const int tid = threadIdx.x;
    const int tx = tid & 15, ty = tid >> 4;
    const int m0 = blockIdx.y * BM, n0 = blockIdx.x * BNT;
    const int a_m = tid >> 2, a_k = (tid & 3) * 4;
    const int b_k = tid >> 4, b_n = (tid & 15) * 4;

    float acc[4][4] = {};
    for (int k0 = 0; k0 < K; k0 += BKT) {
        float4 av = *(const float4*)&A[(size_t)(m0 + a_m) * K + k0 + a_k];
        As[a_k + 0][a_m] = av.x; As[a_k + 1][a_m] = av.y;
        As[a_k + 2][a_m] = av.z; As[a_k + 3][a_m] = av.w;
        float4 bv = *(const float4*)&B[(size_t)(k0 + b_k) * N + n0 + b_n];
        *(float4*)&Bs[b_k][b_n] = bv;
        __syncthreads();
#pragma unroll
        for (int k = 0; k < BKT; k++) {
            float ar[4], br[4];
#pragma unroll
            for (int i = 0; i < 4; i++) ar[i] = As[k][ty * 4 + i];
#pragma unroll
            for (int j = 0; j < 4; j++) br[j] = Bs[k][tx * 4 + j];
#pragma unroll
            for (int i = 0; i < 4; i++)
#pragma unroll
                for (int j = 0; j < 4; j++) acc[i][j] = fmaf(ar[i], br[j], acc[i][j]);
        }
        __syncthreads();
    }
#pragma unroll
    for (int i = 0; i < 4; i++) {
        int m = m0 + ty * 4 + i;
#pragma unroll
        for (int j = 0; j < 4; j++) {
            int n = n0 + tx * 4 + j;
            float v = acc[i][j];
            if (EPI == 1) v += bias[n];
            if (EPI == 2) v = fmaxf(v + bias[n], 0.0f);
            if (EPI == 3) v = gelu_exact((v + bias[n]) * gam[n] + bet[n]);
            if (EPI == 4) v = res[(size_t)m * N + n] + (v + bias[n]) * gam[n] + bet[n];
            C[(size_t)m * N + n] = v;
        }
    }
}

// ---------------- stem: implicit im2col GEMM ----------------
// nf[m][c] = sum_k x_patch[m][k] * Wt[k][c] + stem_b[c] + pos[c*576 + (m%576)]
__global__ __launch_bounds__(256) void stem_gemm_kernel(
    const float* __restrict__ X, const float* __restrict__ Bw, float* __restrict__ C,
    const float* __restrict__ bias, const float* __restrict__ pos)
{
    const int Kd = 768, Nd = 192;
    __shared__ float As[BKT][BM];
    __shared__ float Bs[BKT][BNT];
    const int tid = threadIdx.x;
    const int tx = tid & 15, ty = tid >> 4;
    const int m0 = blockIdx.y * BM, n0 = blockIdx.x * BNT;
    const int a_m = tid >> 2, a_k = (tid & 3) * 4;
    const int b_k = tid >> 4, b_n = (tid & 15) * 4;

    const int m = m0 + a_m;
    const int bimg = m / NNODE;
    const int nsp = m % NNODE;
    const int py = nsp / HGRID, px = nsp % HGRID;
    const float* xbase = X + (size_t)bimg * 3 * IMGSZ * IMGSZ
                           + (size_t)(py * PATCH) * IMGSZ + px * PATCH;

    float acc[4][4] = {};
    for (int k0 = 0; k0 < Kd; k0 += BKT) {
        int k = k0 + a_k;
        int ci = k >> 8;
        int ky = (k >> 4) & 15;
        int kx = k & 15;   // 0,4,8,12 -> contiguous float4
        float4 av = *(const float4*)&xbase[(size_t)ci * IMGSZ * IMGSZ + ky * IMGSZ + kx];
        As[a_k + 0][a_m] = av.x; As[a_k + 1][a_m] = av.y;
        As[a_k + 2][a_m] = av.z; As[a_k + 3][a_m] = av.w;
        float4 bv = *(const float4*)&Bw[(size_t)(k0 + b_k) * Nd + n0 + b_n];
        *(float4*)&Bs[b_k][b_n] = bv;
        __syncthreads();
#pragma unroll
        for (int k2 = 0; k2 < BKT; k2++) {
            float ar[4], br[4];
#pragma unroll
            for (int i = 0; i < 4; i++) ar[i] = As[k2][ty * 4 + i];
#pragma unroll
            for (int j = 0; j < 4; j++) br[j] = Bs[k2][tx * 4 + j];
#pragma unroll
            for (int i = 0; i < 4; i++)
#pragma unroll
                for (int j = 0; j < 4; j++) acc[i][j] = fmaf(ar[i], br[j], acc[i][j]);
        }
        __syncthreads();
    }
#pragma unroll
    for (int i = 0; i < 4; i++) {
        int mm = m0 + ty * 4 + i;
        int sp = mm % NNODE;
#pragma unroll
        for (int j = 0; j < 4; j++) {
            int n = n0 + tx * 4 + j;
            C[(size_t)mm * Nd + n] = acc[i][j] + bias[n] + pos[n * NNODE + sp];
        }
    }
}

// ---------------- transpose stem weight [192,768] -> [768,192] ----------------
__global__ void transpose_w_kernel(const float* __restrict__ w, float* __restrict__ wt) {
    int i = blockIdx.x * blockDim.x + threadIdx.x;
    if (i >= 192 * 768) return;
    int n = i / 768, k = i % 768;
    wt[k * 192 + n] = w[i];
}

// ---------------- per-node squared norm ----------------
__global__ void sq_kernel(const float* __restrict__ nf, float* __restrict__ sq) {
    int node = (blockIdx.x * blockDim.x + threadIdx.x) >> 5;
    int lane = threadIdx.x & 31;
    if (node >= BN) return;
    float s = 0.f;
#pragma unroll
    for (int j = 0; j < 6; j++) {
        float x = nf[(size_t)node * CH + lane + 32 * j];
        s = fmaf(x, x, s);
    }
#pragma unroll
    for (int off = 16; off; off >>= 1) s += __shfl_down_sync(0xffffffffu, s, off);
    if (lane == 0) sq[node] = s;
}

// ---------------- per-image Gram -> ranking score ----------------
// score[row][col] = sq[col] - 2*dot(row,col)  (sq[row] constant per row, dropped)
__global__ __launch_bounds__(256) void gram_kernel(
    const float* __restrict__ nf, const float* __restrict__ sq, float* __restrict__ d2)
{
    const int b = blockIdx.z;
    const float* A = nf + (size_t)b * NNODE * CH;
    __shared__ float As[BKT][BM];
    __shared__ float Bs[BKT][BNT];
    const int tid = threadIdx.x;
    const int tx = tid & 15, ty = tid >> 4;
    const int r0 = blockIdx.y * 64, c0 = blockIdx.x * 64;
    const int l_m = tid >> 2, l_k = (tid & 3) * 4;

    float acc[4][4] = {};
    for (int k0 = 0; k0 < CH; k0 += BKT) {
        float4 av = *(const float4*)&A[(size_t)(r0 + l_m) * CH + k0 + l_k];
        As[l_k + 0][l_m] = av.x; As[l_k + 1][l_m] = av.y;
        As[l_k + 2][l_m] = av.z; As[l_k + 3][l_m] = av.w;
        float4 bv = *(const float4*)&A[(size_t)(c0 + l_m) * CH + k0 + l_k];
        Bs[l_k + 0][l_m] = bv.x; Bs[l_k + 1][l_m] = bv.y;
        Bs[l_k + 2][l_m] = bv.z; Bs[l_k + 3][l_m] = bv.w;
        __syncthreads();
#pragma unroll
        for (int k = 0; k < BKT; k++) {
            float ar[4], br[4];
#pragma unroll
            for (int i = 0; i < 4; i++) ar[i] = As[k][ty * 4 + i];
#pragma unroll
            for (int j = 0; j < 4; j++) br[j] = Bs[k][tx * 4 + j];
#pragma unroll
            for (int i = 0; i < 4; i++)
#pragma unroll
                for (int j = 0; j < 4; j++) acc[i][j] = fmaf(ar[i], br[j], acc[i][j]);
        }
        __syncthreads();
    }
#pragma unroll
    for (int i = 0; i < 4; i++) {
        int r = r0 + ty * 4 + i;
#pragma unroll
        for (int j = 0; j < 4; j++) {
            int c = c0 + tx * 4 + j;
            float v = sq[b * NNODE + c] - 2.0f * acc[i][j];
            if (r == c) v = 3.0e38f;   // exclude self
            d2[((size_t)b * NNODE + r) * NNODE + c] = v;
        }
    }
}

// ---------------- top-5 (ascending distance, lowest-index ties) ----------------
__global__ void topk_kernel(const float* __restrict__ d2, int* __restrict__ idx) {
    int row = (blockIdx.x * blockDim.x + threadIdx.x) >> 5;
    int lane = threadIdx.x & 31;
    if (row >= BN) return;
    const float* r = d2 + (size_t)row * NNODE;
    float v[18];
#pragma unroll
    for (int j = 0; j < 18; j++) v[j] = r[lane + 32 * j];
    int bimg = row / NNODE;
#pragma unroll
    for (int s = 0; s < 5; s++) {
        float bv = 3.4e38f; int bc = 1 << 30;
#pragma unroll
        for (int j = 0; j < 18; j++) {
            int c = lane + 32 * j;
            if (v[j] < bv) { bv = v[j]; bc = c; }   // ascending c -> lowest idx on tie
        }
#pragma unroll
        for (int off = 16; off; off >>= 1) {
            float ov = __shfl_down_sync(0xffffffffu, bv, off);
            int   oc = __shfl_down_sync(0xffffffffu, bc, off);
            if (ov < bv || (ov == bv && oc < bc)) { bv = ov; bc = oc; }
        }
        bc = __shfl_sync(0xffffffffu, bc, 0);
        if ((bc & 31) == lane) v[bc >> 5] = 3.4e38f;
        if (lane == 0) idx[row * KNN + s] = bimg * NNODE + bc;
    }
}

// ---------------- edge attention (P[src]+Q[dst] already has b1 in Q) ----------------
__global__ void edge_kernel(const float* __restrict__ P, const float* __restrict__ Q,
                            const int* __restrict__ idx,
                            const float* __restrict__ w2, const float* __restrict__ b2,
                            float* __restrict__ att, float* __restrict__ out)
{
    int e = (blockIdx.x * blockDim.x + threadIdx.x) >> 5;
    int lane = threadIdx.x & 31;
    if (e >= EDG) return;
    int dst = e / KNN;
    int src = idx[e];
    float s = 0.f;
#pragma unroll
    for (int j = 0; j < 6; j++) {
        int c = lane + 32 * j;
        float x = P[(size_t)src * CH + c] + Q[(size_t)dst * CH + c];
        x = fmaxf(x, 0.f);
        s = fmaf(x, w2[c], s);
    }
#pragma unroll
    for (int off = 16; off; off >>= 1) s += __shfl_down_sync(0xffffffffu, s, off);
    if (lane == 0) {
        float a = 1.0f / (1.0f + expf(-(s + b2[0])));
        att[e] = a;
        out[e] = a;
    }
}

// ---------------- 5-neighbor attention-weighted aggregate + residual ----------------
__global__ void agg_kernel(const float* __restrict__ h, const int* __restrict__ idx,
                           const float* __restrict__ att, float* __restrict__ hm)
{
    int i = blockIdx.x;
    int c = threadIdx.x;
    float acc = h[(size_t)i * CH + c];
#pragma unroll
    for (int k = 0; k < KNN; k++) {
        int nb = idx[i * KNN + k];
        float a = att[i * KNN + k];
        acc = fmaf(a, h[(size_t)nb * CH + c], acc);
    }
    hm[(size_t)i * CH + c] = acc;
}

// ---------------- global mean pool over nodes ----------------
__global__ void pool_kernel(const float* __restrict__ t, float* __restrict__ g) {
    int b = blockIdx.x, c = threadIdx.x;
    float acc = 0.f;
    for (int n = 0; n < NNODE; n++) acc += t[((size_t)b * NNODE + n) * CH + c];
    g[b * CH + c] = acc * (1.0f / NNODE);
}

// ---------------- final 1024 -> 1 dot ----------------
__global__ void pred_final_kernel(const float* __restrict__ p, const float* __restrict__ w2,
                                  const float* __restrict__ b2, float* __restrict__ out)
{
    int b = blockIdx.x, tid = threadIdx.x;
    float s = 0.f;
    for (int i = tid; i < PHID; i += 256) s = fmaf(p[(size_t)b * PHID + i], w2[i], s);
    __shared__ float red[256];
    red[tid] = s; __syncthreads();
    for (int st = 128; st; st >>= 1) { if (tid < st) red[tid] += red[tid + st]; __syncthreads(); }
    if (tid == 0) out[b] = red[0] + b2[0];
}

// ---------------- host launch ----------------
extern "C" void kernel_launch(void* const* d_in, const int* in_sizes, int n_in,
                              void* d_out, int out_size)
{
    const float* x        = (const float*)d_in[0];
    const float* stem_w   = (const float*)d_in[1];
    const float* stem_b   = (const float*)d_in[2];
    const float* pos      = (const float*)d_in[3];
    const float* att_w1   = (const float*)d_in[4];
    const float* att_b1   = (const float*)d_in[5];
    const float* att_w2   = (const float*)d_in[6];
    const float* att_b2   = (const float*)d_in[7];
    const float* gnn_w1   = (const float*)d_in[8];
    const float* gnn_b1   = (const float*)d_in[9];
    const float* gnn_w2   = (const float*)d_in[10];
    const float* gnn_b2   = (const float*)d_in[11];
    const float* ffn_w1   = (const float*)d_in[12];
    const float* ffn_b1   = (const float*)d_in[13];
    const float* ffn_g1   = (const float*)d_in[14];
    const float* ffn_be1  = (const float*)d_in[15];
    const float* ffn_w2   = (const float*)d_in[16];
    const float* ffn_b2   = (const float*)d_in[17];
    const float* ffn_g2   = (const float*)d_in[18];
    const float* ffn_be2  = (const float*)d_in[19];
    const float* pred_w1  = (const float*)d_in[20];
    const float* pred_b1  = (const float*)d_in[21];
    const float* pred_g   = (const float*)d_in[22];
    const float* pred_be  = (const float*)d_in[23];
    const float* pred_w2  = (const float*)d_in[24];
    const float* pred_b2  = (const float*)d_in[25];
    float* out = (float*)d_out;

    float *p_wt, *p_nf, *p_sq, *p_d2, *p_P, *p_Q, *p_att, *p_h, *p_hm, *p_u, *p_t, *p_g, *p_p;
    int* p_idx;
    cudaGetSymbolAddress((void**)&p_wt,  g_wt);
    cudaGetSymbolAddress((void**)&p_nf,  g_nf);
    cudaGetSymbolAddress((void**)&p_sq,  g_sq);
    cudaGetSymbolAddress((void**)&p_d2,  g_d2);
    cudaGetSymbolAddress((void**)&p_idx, g_idx);
    cudaGetSymbolAddress((void**)&p_P,   g_P);
    cudaGetSymbolAddress((void**)&p_Q,   g_Q);
    cudaGetSymbolAddress((void**)&p_att, g_att);
    cudaGetSymbolAddress((void**)&p_h,   g_h);
    cudaGetSymbolAddress((void**)&p_hm,  g_hm);
    cudaGetSymbolAddress((void**)&p_u,   g_u);
    cudaGetSymbolAddress((void**)&p_t,   g_t);
    cudaGetSymbolAddress((void**)&p_g,   g_g);
    cudaGetSymbolAddress((void**)&p_p,   g_p);

    // 1) transpose stem weight
    transpose_w_kernel<<<(192 * 768 + 255) / 256, 256>>>(stem_w, p_wt);
    // 2) stem conv as implicit GEMM  [36864 x 192] = [36864 x 768] @ [768 x 192]
    stem_gemm_kernel<<<dim3(192 / BNT, BN / BM), 256>>>(x, p_wt, p_nf, stem_b, pos);
    // 3) squared norms
    sq_kernel<<<(BN * 32 + 255) / 256, 256>>>(p_nf, p_sq);
    // 4) per-image distance scores
    gram_kernel<<<dim3(NNODE / 64, NNODE / 64, Bsz), 256>>>(p_nf, p_sq, p_d2);
    // 5) top-5 neighbors
    topk_kernel<<<(BN * 32 + 255) / 256, 256>>>(p_d2, p_idx);
    // 6) P = nf @ W1[:192]   (no bias)
    sgemm_kernel<0><<<dim3(CH / BNT, BN / BM), 256>>>(p_nf, att_w1, p_P, BN, CH, CH,
                                                      nullptr, nullptr, nullptr, nullptr);
    // 7) Q = nf @ W1[192:] + b1
    sgemm_kernel<1><<<dim3(CH / BNT, BN / BM), 256>>>(p_nf, att_w1 + 192 * 192, p_Q, BN, CH, CH,
                                                      att_b1, nullptr, nullptr, nullptr);
    // 8) edge attention -> g_att and d_out[0:E]
    edge_kernel<<<(EDG * 32 + 255) / 256, 256>>>(p_P, p_Q, p_idx, att_w2, att_b2, p_att, out);
    // 9) GNN layer 1
    agg_kernel<<<BN, CH>>>(p_nf, p_idx, p_att, p_hm);
    sgemm_kernel<2><<<dim3(CH / BNT, BN / BM), 256>>>(p_hm, gnn_w1, p_h, BN, CH, CH,
                                                      gnn_b1, nullptr, nullptr, nullptr);
    // 10) GNN layer 2
    agg_kernel<<<BN, CH>>>(p_h, p_idx, p_att, p_hm);
    sgemm_kernel<2><<<dim3(CH / BNT, BN / BM), 256>>>(p_hm, gnn_w2, p_h, BN, CH, CH,
                                                      gnn_b2, nullptr, nullptr, nullptr);
    // 11) FFN
    sgemm_kernel<3><<<dim3(HID / BNT, BN / BM), 256>>>(p_h, ffn_w1, p_u, BN, HID, CH,
                                                       ffn_b1, ffn_g1, ffn_be1, nullptr);
    sgemm_kernel<4><<<dim3(CH / BNT, BN / BM), 256>>>(p_u, ffn_w2, p_t, BN, CH, HID,
                                                      ffn_b2, ffn_g2, ffn_be2, p_h);
    // 12) pool + prediction head
    pool_kernel<<<Bsz, CH>>>(p_t, p_g);
    sgemm_kernel<3><<<dim3(PHID / BNT, Bsz / BM), 256>>>(p_g, pred_w1, p_p, Bsz, PHID, CH,
                                                         pred_b1, pred_g, pred_be, nullptr);
    pred_final_kernel<<<Bsz, 256>>>(p_p, pred_w2, pred_b2, out + EDG);
}

// round 2
// speedup vs baseline: 1.1837x; 1.1837x over previous
#include <cuda_runtime.h>
#include <cuda_bf16.h>
#include <math.h>

// ---------------- problem constants ----------------
#define Bsz   64
#define IMGSZ 384
#define PATCH 16
#define CH    192
#define KNN   5
#define HGRID 24
#define NNODE 576            // per image
#define BN    (Bsz * NNODE)  // 36864 global nodes
#define EDG   (BN * KNN)     // 184320 edges
#define HID   768
#define PHID  1024

// ---------------- scratch (no allocations allowed) ----------------
__device__ float g_wt  [768 * 192];
__device__ float g_nf  [(size_t)BN * CH];
__device__ float g_sq  [BN];
__device__ float g_d2  [(size_t)Bsz * NNODE * NNODE];
__device__ int   g_idx [BN * KNN];
__device__ float g_P   [(size_t)BN * CH];
__device__ float g_Q   [(size_t)BN * CH];
__device__ float g_att [EDG];
__device__ float g_h   [(size_t)BN * CH];
__device__ float g_hm  [(size_t)BN * CH];
__device__ float g_u   [(size_t)BN * HID];
__device__ float g_t   [(size_t)BN * CH];
__device__ float g_g   [Bsz * CH];
__device__ float g_p   [Bsz * PHID];

__device__ __forceinline__ float gelu_exact(float v) {
    return 0.5f * v * (1.0f + erff(v * 0.70710678118654752f));
}

// =================================================================
// gemm128: C[M,N] = A[M,K] @ B[K,N]; 128x64 tile, 8x4 microtile,
// double-buffered smem.  M%128==0, N%64==0, K%16==0.
// EPI: 0=none, 1=+bias, 2=relu(+bias), 3=gelu((x+b)*g+be), 4=res+(x+b)*g+be
// =================================================================
#define GBM 128
#define GBN 64
#define GBK 16

template <int EPI>
__global__ __launch_bounds__(256) void gemm128_kernel(
    const float* __restrict__ A, const float* __restrict__ B, float* __restrict__ C,
    int M, int N, int K,
    const float* __restrict__ bias, const float* __restrict__ gam,
    const float* __restrict__ bet,  const float* __restrict__ res)
{
    __shared__ float As[2][GBK][GBM];
    __shared__ float Bs[2][GBK][GBN];
    const int tid = threadIdx.x;
    const int tx = tid & 15, ty = tid >> 4;          // 16x16 thread grid
    const int m0 = blockIdx.y * GBM, n0 = blockIdx.x * GBN;
    const int a_m = tid >> 1, a_k = (tid & 1) * 8;   // A: 2 float4 along k
    const int b_k = tid >> 4, b_n = (tid & 15) * 4;  // B: 1 float4 along n

    const float* Ap = A + (size_t)(m0 + a_m) * K + a_k;
    const float* Bp = B + (size_t)b_k * N + n0 + b_n;

    float4 a0 = *(const float4*)Ap;
    float4 a1 = *(const float4*)(Ap + 4);
    float4 bv = *(const float4*)Bp;

    As[0][a_k + 0][a_m] = a0.x; As[0][a_k + 1][a_m] = a0.y;
    As[0][a_k + 2][a_m] = a0.z; As[0][a_k + 3][a_m] = a0.w;
    As[0][a_k + 4][a_m] = a1.x; As[0][a_k + 5][a_m] = a1.y;
    As[0][a_k + 6][a_m] = a1.z; As[0][a_k + 7][a_m] = a1.w;
    *(float4*)&Bs[0][b_k][b_n] = bv;
    __syncthreads();

    float acc[8][4] = {};
    int buf = 0;
    for (int k0 = GBK; ; k0 += GBK) {
        const bool more = (k0 < K);
        if (more) {
            a0 = *(const float4*)(Ap + k0);
            a1 = *(const float4*)(Ap + k0 + 4);
            bv = *(const float4*)(Bp + (size_t)k0 * N);
        }
#pragma unroll
        for (int k = 0; k < GBK; k++) {
            float ar[8], br[4];
            *(float4*)&ar[0] = *(float4*)&As[buf][k][ty * 8];
            *(float4*)&ar[4] = *(float4*)&As[buf][k][ty * 8 + 4];
            *(float4*)&br[0] = *(float4*)&Bs[buf][k][tx * 4];
#pragma unroll
            for (int i = 0; i < 8; i++)
#pragma unroll
                for (int j = 0; j < 4; j++) acc[i][j] = fmaf(ar[i], br[j], acc[i][j]);
        }
        if (!more) break;
        const int nb = buf ^ 1;
        As[nb][a_k + 0][a_m] = a0.x; As[nb][a_k + 1][a_m] = a0.y;
        As[nb][a_k + 2][a_m] = a0.z; As[nb][a_k + 3][a_m] = a0.w;
        As[nb][a_k + 4][a_m] = a1.x; As[nb][a_k + 5][a_m] = a1.y;
        As[nb][a_k + 6][a_m] = a1.z; As[nb][a_k + 7][a_m] = a1.w;
        *(float4*)&Bs[nb][b_k][b_n] = bv;
        __syncthreads();
        buf = nb;
    }

#pragma unroll
    for (int i = 0; i < 8; i++) {
        int m = m0 + ty * 8 + i;
#pragma unroll
        for (int j = 0; j < 4; j++) {
            int n = n0 + tx * 4 + j;
            float v = acc[i][j];
            if (EPI == 1) v += bias[n];
            if (EPI == 2) v = fmaxf(v + bias[n], 0.0f);
            if (EPI == 3) v = gelu_exact((v + bias[n]) * gam[n] + bet[n]);
            if (EPI == 4) v = res[(size_t)m * N + n] + (v + bias[n]) * gam[n] + bet[n];
            C[(size_t)m * N + n] = v;
        }
    }
}

// =================================================================
// stem: implicit im2col GEMM, 128x64 tile, 8x4 microtile, dbl-buffered
// =================================================================
__global__ __launch_bounds__(256) void stem_gemm_kernel(
    const float* __restrict__ X, const float* __restrict__ Bw, float* __restrict__ C,
    const float* __restrict__ bias, const float* __restrict__ pos)
{
    const int Kd = 768, Nd = 192;
    __shared__ float As[2][GBK][GBM];
    __shared__ float Bs[2][GBK][GBN];
    const int tid = threadIdx.x;
    const int tx = tid & 15, ty = tid >> 4;
    const int m0 = blockIdx.y * GBM, n0 = blockIdx.x * GBN;
    const int a_m = tid >> 1, a_k = (tid & 1) * 8;
    const int b_k = tid >> 4, b_n = (tid & 15) * 4;

    const int m = m0 + a_m;
    const int bimg = m / NNODE;
    const int nsp = m % NNODE;
    const int py = nsp / HGRID, px = nsp % HGRID;
    const float* xbase = X + (size_t)bimg * 3 * IMGSZ * IMGSZ
                           + (size_t)(py * PATCH) * IMGSZ + px * PATCH;
    const float* Bp = Bw + (size_t)b_k * Nd + n0 + b_n;

    // k -> (ci, ky, kx): ci=k>>8, ky=(k>>4)&15, kx=k&15 (contiguous in kx)
    auto aptr = [&](int k) -> const float* {
        int ci = k >> 8, ky = (k >> 4) & 15, kx = k & 15;
        return xbase + (size_t)ci * IMGSZ * IMGSZ + ky * IMGSZ + kx;
    };

    const float* xr = aptr(a_k);
    float4 a0 = *(const float4*)xr;
    float4 a1 = *(const float4*)(xr + 4);
    float4 bv = *(const float4*)Bp;

    As[0][a_k + 0][a_m] = a0.x; As[0][a_k + 1][a_m] = a0.y;
    As[0][a_k + 2][a_m] = a0.z; As[0][a_k + 3][a_m] = a0.w;
    As[0][a_k + 4][a_m] = a1.x; As[0][a_k + 5][a_m] = a1.y;
    As[0][a_k + 6][a_m] = a1.z; As[0][a_k + 7][a_m] = a1.w;
    *(float4*)&Bs[0][b_k][b_n] = bv;
    __syncthreads();

    float acc[8][4] = {};
    int buf = 0;
    for (int k0 = GBK; ; k0 += GBK) {
        const bool more = (k0 < Kd);
        if (more) {
            const float* xn = aptr(k0 + a_k);
            a0 = *(const float4*)xn;
            a1 = *(const float4*)(xn + 4);
            bv = *(const float4*)(Bp + (size_t)k0 * Nd);
        }
#pragma unroll
        for (int k = 0; k < GBK; k++) {
            float ar[8], br[4];
            *(float4*)&ar[0] = *(float4*)&As[buf][k][ty * 8];
            *(float4*)&ar[4] = *(float4*)&As[buf][k][ty * 8 + 4];
            *(float4*)&br[0] = *(float4*)&Bs[buf][k][tx * 4];
#pragma unroll
            for (int i = 0; i < 8; i++)
#pragma unroll
                for (int j = 0; j < 4; j++) acc[i][j] = fmaf(ar[i], br[j], acc[i][j]);
        }
        if (!more) break;
        const int nb = buf ^ 1;
        As[nb][a_k + 0][a_m] = a0.x; As[nb][a_k + 1][a_m] = a0.y;
        As[nb][a_k + 2][a_m] = a0.z; As[nb][a_k + 3][a_m] = a0.w;
        As[nb][a_k + 4][a_m] = a1.x; As[nb][a_k + 5][a_m] = a1.y;
        As[nb][a_k + 6][a_m] = a1.z; As[nb][a_k + 7][a_m] = a1.w;
        *(float4*)&Bs[nb][b_k][b_n] = bv;
        __syncthreads();
        buf = nb;
    }

#pragma unroll
    for (int i = 0; i < 8; i++) {
        int mm = m0 + ty * 8 + i;
        int sp = mm % NNODE;
#pragma unroll
        for (int j = 0; j < 4; j++) {
            int n = n0 + tx * 4 + j;
            C[(size_t)mm * CH + n] = acc[i][j] + bias[n] + pos[n * NNODE + sp];
        }
    }
}

// =================================================================
// gram: per-image 64x64 tile, 8x4 microtile, 128 threads, dbl-buffered
// score[r][c] = sq[c] - 2*dot(r,c); diag = +inf
// =================================================================
__global__ __launch_bounds__(128) void gram2_kernel(
    const float* __restrict__ nf, const float* __restrict__ sq, float* __restrict__ d2)
{
    const int b = blockIdx.z;
    const float* Ab = nf + (size_t)b * NNODE * CH;
    __shared__ float As[2][GBK][64];
    __shared__ float Bs[2][GBK][64];
    const int tid = threadIdx.x;
    const int tx = tid & 15, ty = tid >> 4;          // 8 row-groups x 16 col-groups
    const int r0 = blockIdx.y * 64, c0 = blockIdx.x * 64;
    const int l_m = tid >> 1, l_k = (tid & 1) * 8;   // 2 float4 along k per tile

    const float* Apt = Ab + (size_t)(r0 + l_m) * CH + l_k;
    const float* Bpt = Ab + (size_t)(c0 + l_m) * CH + l_k;

    float4 a0 = *(const float4*)Apt;
    float4 a1 = *(const float4*)(Apt + 4);
    float4 c0v = *(const float4*)Bpt;
    float4 c1v = *(const float4*)(Bpt + 4);

    As[0][l_k + 0][l_m] = a0.x; As[0][l_k + 1][l_m] = a0.y;
    As[0][l_k + 2][l_m] = a0.z; As[0][l_k + 3][l_m] = a0.w;
    As[0][l_k + 4][l_m] = a1.x; As[0][l_k + 5][l_m] = a1.y;
    As[0][l_k + 6][l_m] = a1.z; As[0][l_k + 7][l_m] = a1.w;
    Bs[0][l_k + 0][l_m] = c0v.x; Bs[0][l_k + 1][l_m] = c0v.y;
    Bs[0][l_k + 2][l_m] = c0v.z; Bs[0][l_k + 3][l_m] = c0v.w;
    Bs[0][l_k + 4][l_m] = c1v.x; Bs[0][l_k + 5][l_m] = c1v.y;
    Bs[0][l_k + 6][l_m] = c1v.z; Bs[0][l_k + 7][l_m] = c1v.w;
    __syncthreads();

    float acc[8][4] = {};
    int buf = 0;
    for (int k0 = GBK; ; k0 += GBK) {
        const bool more = (k0 < CH);
        if (more) {
            a0  = *(const float4*)(Apt + k0);
            a1  = *(const float4*)(Apt + k0 + 4);
            c0v = *(const float4*)(Bpt + k0);
            c1v = *(const float4*)(Bpt + k0 + 4);
        }
#pragma unroll
        for (int k = 0; k < GBK; k++) {
            float ar[8], br[4];
            *(float4*)&ar[0] = *(float4*)&As[buf][k][ty * 8];
            *(float4*)&ar[4] = *(float4*)&As[buf][k][ty * 8 + 4];
            *(float4*)&br[0] = *(float4*)&Bs[buf][k][tx * 4];
#pragma unroll
            for (int i = 0; i < 8; i++)
#pragma unroll
                for (int j = 0; j < 4; j++) acc[i][j] = fmaf(ar[i], br[j], acc[i][j]);
        }
        if (!more) break;
        const int nb = buf ^ 1;
        As[nb][l_k + 0][l_m] = a0.x; As[nb][l_k + 1][l_m] = a0.y;
        As[nb][l_k + 2][l_m] = a0.z; As[nb][l_k + 3][l_m] = a0.w;
        As[nb][l_k + 4][l_m] = a1.x; As[nb][l_k + 5][l_m] = a1.y;
        As[nb][l_k + 6][l_m] = a1.z; As[nb][l_k + 7][l_m] = a1.w;
        Bs[nb][l_k + 0][l_m] = c0v.x; Bs[nb][l_k + 1][l_m] = c0v.y;
        Bs[nb][l_k + 2][l_m] = c0v.z; Bs[nb][l_k + 3][l_m] = c0v.w;
        Bs[nb][l_k + 4][l_m] = c1v.x; Bs[nb][l_k + 5][l_m] = c1v.y;
        Bs[nb][l_k + 6][l_m] = c1v.z; Bs[nb][l_k + 7][l_m] = c1v.w;
        __syncthreads();
        buf = nb;
    }

#pragma unroll
    for (int i = 0; i < 8; i++) {
        int r = r0 + ty * 8 + i;
#pragma unroll
        for (int j = 0; j < 4; j++) {
            int c = c0 + tx * 4 + j;
            float v = sq[b * NNODE + c] - 2.0f * acc[i][j];
            if (r == c) v = 3.0e38f;
            d2[((size_t)b * NNODE + r) * NNODE + c] = v;
        }
    }
}

// ---------------- small-M SGEMM kept for pred head (M=64) ----------------
#define BM 64
#define BNT 64
#define BKT 16
template <int EPI>
__global__ __launch_bounds__(256) void sgemm_kernel(
    const float* __restrict__ A, const float* __restrict__ B, float* __restrict__ C,
    int M, int N, int K,
    const float* __restrict__ bias, const float* __restrict__ gam,
    const float* __restrict__ bet,  const float* __restrict__ res)
{
    __shared__ float As[BKT][BM];
    __shared__ float Bs[BKT][BNT];
    const int tid = threadIdx.x;
    const int tx = tid & 15, ty = tid >> 4;
    const int m0 = blockIdx.y * BM, n0 = blockIdx.x * BNT;
    const int a_m = tid >> 2, a_k = (tid & 3) * 4;
    const int b_k = tid >> 4, b_n = (tid & 15) * 4;

    float acc[4][4] = {};
    for (int k0 = 0; k0 < K; k0 += BKT) {
        float4 av = *(const float4*)&A[(size_t)(m0 + a_m) * K + k0 + a_k];
        As[a_k + 0][a_m] = av.x; As[a_k + 1][a_m] = av.y;
        As[a_k + 2][a_m] = av.z; As[a_k + 3][a_m] = av.w;
        float4 bv = *(const float4*)&B[(size_t)(k0 + b_k) * N + n0 + b_n];
        *(float4*)&Bs[b_k][b_n] = bv;
        __syncthreads();
#pragma unroll
        for (int k = 0; k < BKT; k++) {
            float ar[4], br[4];
#pragma unroll
            for (int i = 0; i < 4; i++) ar[i] = As[k][ty * 4 + i];
#pragma unroll
            for (int j = 0; j < 4; j++) br[j] = Bs[k][tx * 4 + j];
#pragma unroll
            for (int i = 0; i < 4; i++)
#pragma unroll
                for (int j = 0; j < 4; j++) acc[i][j] = fmaf(ar[i], br[j], acc[i][j]);
        }
        __syncthreads();
    }
#pragma unroll
    for (int i = 0; i < 4; i++) {
        int m = m0 + ty * 4 + i;
#pragma unroll
        for (int j = 0; j < 4; j++) {
            int n = n0 + tx * 4 + j;
            float v = acc[i][j];
            if (EPI == 1) v += bias[n];
            if (EPI == 2) v = fmaxf(v + bias[n], 0.0f);
            if (EPI == 3) v = gelu_exact((v + bias[n]) * gam[n] + bet[n]);
            if (EPI == 4) v = res[(size_t)m * N + n] + (v + bias[n]) * gam[n] + bet[n];
            C[(size_t)m * N + n] = v;
        }
    }
}

// ---------------- auxiliary kernels ----------------
__global__ void transpose_w_kernel(const float* __restrict__ w, float* __restrict__ wt) {
    int i = blockIdx.x * blockDim.x + threadIdx.x;
    if (i >= 192 * 768) return;
    int n = i / 768, k = i % 768;
    wt[k * 192 + n] = w[i];
}

__global__ void sq_kernel(const float* __restrict__ nf, float* __restrict__ sq) {
    int node = (blockIdx.x * blockDim.x + threadIdx.x) >> 5;
    int lane = threadIdx.x & 31;
    if (node >= BN) return;
    float s = 0.f;
#pragma unroll
    for (int j = 0; j < 6; j++) {
        float x = nf[(size_t)node * CH + lane + 32 * j];
        s = fmaf(x, x, s);
    }
#pragma unroll
    for (int off = 16; off; off >>= 1) s += __shfl_down_sync(0xffffffffu, s, off);
    if (lane == 0) sq[node] = s;
}

__global__ void topk_kernel(const float* __restrict__ d2, int* __restrict__ idx) {
    int row = (blockIdx.x * blockDim.x + threadIdx.x) >> 5;
    int lane = threadIdx.x & 31;
    if (row >= BN) return;
    const float* r = d2 + (size_t)row * NNODE;
    float v[18];
#pragma unroll
    for (int j = 0; j < 18; j++) v[j] = r[lane + 32 * j];
    int bimg = row / NNODE;
#pragma unroll
    for (int s = 0; s < 5; s++) {
        float bv = 3.4e38f; int bc = 1 << 30;
#pragma unroll
        for (int j = 0; j < 18; j++) {
            int c = lane + 32 * j;
            if (v[j] < bv) { bv = v[j]; bc = c; }
        }
#pragma unroll
        for (int off = 16; off; off >>= 1) {
            float ov = __shfl_down_sync(0xffffffffu, bv, off);
            int   oc = __shfl_down_sync(0xffffffffu, bc, off);
            if (ov < bv || (ov == bv && oc < bc)) { bv = ov; bc = oc; }
        }
        bc = __shfl_sync(0xffffffffu, bc, 0);
        if ((bc & 31) == lane) v[bc >> 5] = 3.4e38f;
        if (lane == 0) idx[row * KNN + s] = bimg * NNODE + bc;
    }
}

__global__ void edge_kernel(const float* __restrict__ P, const float* __restrict__ Q,
                            const int* __restrict__ idx,
                            const float* __restrict__ w2, const float* __restrict__ b2,
                            float* __restrict__ att, float* __restrict__ out)
{
    int e = (blockIdx.x * blockDim.x + threadIdx.x) >> 5;
    int lane = threadIdx.x & 31;
    if (e >= EDG) return;
    int dst = e / KNN;
    int src = idx[e];
    float s = 0.f;
#pragma unroll
    for (int j = 0; j < 6; j++) {
        int c = lane + 32 * j;
        float x = P[(size_t)src * CH + c] + Q[(size_t)dst * CH + c];
        x = fmaxf(x, 0.f);
        s = fmaf(x, w2[c], s);
    }
#pragma unroll
    for (int off = 16; off; off >>= 1) s += __shfl_down_sync(0xffffffffu, s, off);
    if (lane == 0) {
        float a = 1.0f / (1.0f + expf(-(s + b2[0])));
        att[e] = a;
        out[e] = a;
    }
}

__global__ void agg_kernel(const float* __restrict__ h, const int* __restrict__ idx,
                           const float* __restrict__ att, float* __restrict__ hm)
{
    int i = blockIdx.x;
    int c = threadIdx.x;
    float acc = h[(size_t)i * CH + c];
#pragma unroll
    for (int k = 0; k < KNN; k++) {
        int nb = idx[i * KNN + k];
        float a = att[i * KNN + k];
        acc = fmaf(a, h[(size_t)nb * CH + c], acc);
    }
    hm[(size_t)i * CH + c] = acc;
}

__global__ void pool_kernel(const float* __restrict__ t, float* __restrict__ g) {
    int b = blockIdx.x, c = threadIdx.x;
    float acc = 0.f;
    for (int n = 0; n < NNODE; n++) acc += t[((size_t)b * NNODE + n) * CH + c];
    g[b * CH + c] = acc * (1.0f / NNODE);
}

__global__ void pred_final_kernel(const float* __restrict__ p, const float* __restrict__ w2,
                                  const float* __restrict__ b2, float* __restrict__ out)
{
    int b = blockIdx.x, tid = threadIdx.x;
    float s = 0.f;
    for (int i = tid; i < PHID; i += 256) s = fmaf(p[(size_t)b * PHID + i], w2[i], s);
    __shared__ float red[256];
    red[tid] = s; __syncthreads();
    for (int st = 128; st; st >>= 1) { if (tid < st) red[tid] += red[tid + st]; __syncthreads(); }
    if (tid == 0) out[b] = red[0] + b2[0];
}

// ---------------- host launch ----------------
extern "C" void kernel_launch(void* const* d_in, const int* in_sizes, int n_in,
                              void* d_out, int out_size)
{
    const float* x        = (const float*)d_in[0];
    const float* stem_w   = (const float*)d_in[1];
    const float* stem_b   = (const float*)d_in[2];
    const float* pos      = (const float*)d_in[3];
    const float* att_w1   = (const float*)d_in[4];
    const float* att_b1   = (const float*)d_in[5];
    const float* att_w2   = (const float*)d_in[6];
    const float* att_b2   = (const float*)d_in[7];
    const float* gnn_w1   = (const float*)d_in[8];
    const float* gnn_b1   = (const float*)d_in[9];
    const float* gnn_w2   = (const float*)d_in[10];
    const float* gnn_b2   = (const float*)d_in[11];
    const float* ffn_w1   = (const float*)d_in[12];
    const float* ffn_b1   = (const float*)d_in[13];
    const float* ffn_g1   = (const float*)d_in[14];
    const float* ffn_be1  = (const float*)d_in[15];
    const float* ffn_w2   = (const float*)d_in[16];
    const float* ffn_b2   = (const float*)d_in[17];
    const float* ffn_g2   = (const float*)d_in[18];
    const float* ffn_be2  = (const float*)d_in[19];
    const float* pred_w1  = (const float*)d_in[20];
    const float* pred_b1  = (const float*)d_in[21];
    const float* pred_g   = (const float*)d_in[22];
    const float* pred_be  = (const float*)d_in[23];
    const float* pred_w2  = (const float*)d_in[24];
    const float* pred_b2  = (const float*)d_in[25];
    float* out = (float*)d_out;

    float *p_wt, *p_nf, *p_sq, *p_d2, *p_P, *p_Q, *p_att, *p_h, *p_hm, *p_u, *p_t, *p_g, *p_p;
    int* p_idx;
    cudaGetSymbolAddress((void**)&p_wt,  g_wt);
    cudaGetSymbolAddress((void**)&p_nf,  g_nf);
    cudaGetSymbolAddress((void**)&p_sq,  g_sq);
    cudaGetSymbolAddress((void**)&p_d2,  g_d2);
    cudaGetSymbolAddress((void**)&p_idx, g_idx);
    cudaGetSymbolAddress((void**)&p_P,   g_P);
    cudaGetSymbolAddress((void**)&p_Q,   g_Q);
    cudaGetSymbolAddress((void**)&p_att, g_att);
    cudaGetSymbolAddress((void**)&p_h,   g_h);
    cudaGetSymbolAddress((void**)&p_hm,  g_hm);
    cudaGetSymbolAddress((void**)&p_u,   g_u);
    cudaGetSymbolAddress((void**)&p_t,   g_t);
    cudaGetSymbolAddress((void**)&p_g,   g_g);
    cudaGetSymbolAddress((void**)&p_p,   g_p);

    transpose_w_kernel<<<(192 * 768 + 255) / 256, 256>>>(stem_w, p_wt);

    // stem conv as implicit GEMM  [36864 x 192] = [36864 x 768] @ [768 x 192]
    stem_gemm_kernel<<<dim3(CH / GBN, BN / GBM), 256>>>(x, p_wt, p_nf, stem_b, pos);

    sq_kernel<<<(BN * 32 + 255) / 256, 256>>>(p_nf, p_sq);

    gram2_kernel<<<dim3(NNODE / 64, NNODE / 64, Bsz), 128>>>(p_nf, p_sq, p_d2);

    topk_kernel<<<(BN * 32 + 255) / 256, 256>>>(p_d2, p_idx);

    // P = nf @ W1[:192], Q = nf @ W1[192:] + b1
    gemm128_kernel<0><<<dim3(CH / GBN, BN / GBM), 256>>>(p_nf, att_w1, p_P, BN, CH, CH,
                                                         nullptr, nullptr, nullptr, nullptr);
    gemm128_kernel<1><<<dim3(CH / GBN, BN / GBM), 256>>>(p_nf, att_w1 + 192 * 192, p_Q, BN, CH, CH,
                                                         att_b1, nullptr, nullptr, nullptr);

    edge_kernel<<<(EDG * 32 + 255) / 256, 256>>>(p_P, p_Q, p_idx, att_w2, att_b2, p_att, out);

    // GNN layer 1
    agg_kernel<<<BN, CH>>>(p_nf, p_idx, p_att, p_hm);
    gemm128_kernel<2><<<dim3(CH / GBN, BN / GBM), 256>>>(p_hm, gnn_w1, p_h, BN, CH, CH,
                                                         gnn_b1, nullptr, nullptr, nullptr);
    // GNN layer 2
    agg_kernel<<<BN, CH>>>(p_h, p_idx, p_att, p_hm);
    gemm128_kernel<2><<<dim3(CH / GBN, BN / GBM), 256>>>(p_hm, gnn_w2, p_h, BN, CH, CH,
                                                         gnn_b2, nullptr, nullptr, nullptr);
    // FFN
    gemm128_kernel<3><<<dim3(HID / GBN, BN / GBM), 256>>>(p_h, ffn_w1, p_u, BN, HID, CH,
                                                          ffn_b1, ffn_g1, ffn_be1, nullptr);
    gemm128_kernel<4><<<dim3(CH / GBN, BN / GBM), 256>>>(p_u, ffn_w2, p_t, BN, CH, HID,
                                                         ffn_b2, ffn_g2, ffn_be2, p_h);
    // pool + prediction head
    pool_kernel<<<Bsz, CH>>>(p_t, p_g);
    sgemm_kernel<3><<<dim3(PHID / BNT, Bsz / BM), 256>>>(p_g, pred_w1, p_p, Bsz, PHID, CH,
                                                         pred_b1, pred_g, pred_be, nullptr);
    pred_final_kernel<<<Bsz, 256>>>(p_p, pred_w2, pred_b2, out + EDG);
}

// round 3
// speedup vs baseline: 1.3840x; 1.1692x over previous
#include <cuda_runtime.h>
#include <cuda_bf16.h>
#include <math.h>
#include <stdint.h>

// ---------------- problem constants ----------------
#define Bsz   64
#define IMGSZ 384
#define PATCH 16
#define CH    192
#define KNN   5
#define HGRID 24
#define NNODE 576
#define BN    (Bsz * NNODE)  // 36864
#define EDG   (BN * KNN)     // 184320
#define HID   768
#define PHID  1024

// ---------------- scratch ----------------
__device__ float g_wt  [768 * 192];
__device__ float g_nf  [(size_t)BN * CH];
__device__ float g_sq  [BN];
__device__ float g_d2  [(size_t)Bsz * NNODE * NNODE];
__device__ int   g_idx [BN * KNN];
__device__ float g_P   [(size_t)BN * CH];
__device__ float g_Q   [(size_t)BN * CH];
__device__ float g_att [EDG];
__device__ float g_h   [(size_t)BN * CH];
__device__ float g_hm  [(size_t)BN * CH];
__device__ float g_u   [(size_t)BN * HID];
__device__ float g_t   [(size_t)BN * CH];
__device__ float g_g   [Bsz * CH];
__device__ float g_p   [Bsz * PHID];

__device__ __forceinline__ float gelu_exact(float v) {
    return 0.5f * v * (1.0f + erff(v * 0.70710678118654752f));
}

__device__ __forceinline__ uint32_t f2tf32(float x) {
    uint32_t r; asm("cvt.rna.tf32.f32 %0, %1;" : "=r"(r) : "f"(x)); return r;
}

// =================================================================
// tf32 tensor-core GEMM (prediction path only).
// C[M,N] = A[M,K] @ B[K,N]; CTA tile 128x64, warp tile 32x32,
// m16n8k8 tf32 mma, fp32 accumulate. M%128==0, N%64==0, K%32==0.
// EPI: 2=relu(+bias), 3=gelu((x+b)*g+be), 4=res+(x+b)*g+be
// =================================================================
template <int EPI>
__global__ __launch_bounds__(256) void tf32gemm_kernel(
    const float* __restrict__ A, const float* __restrict__ B, float* __restrict__ C,
    int M, int N, int K,
    const float* __restrict__ bias, const float* __restrict__ gam,
    const float* __restrict__ bet,  const float* __restrict__ res)
{
    __shared__ uint32_t As[128][36];   // [m][k], stride 36: frag reads conflict-free
    __shared__ uint32_t Bs[64][33];    // [n][k], stride 33: STS conflict-free
    const int tid  = threadIdx.x;
    const int lane = tid & 31, wid = tid >> 5;
    const int wm = (wid >> 1) * 32;     // 4 warps along m
    const int wn = (wid & 1) * 32;      // 2 warps along n
    const int m0 = blockIdx.y * 128, n0 = blockIdx.x * 64;

    const int a_row = tid >> 1;          // 0..127
    const int a_k0  = (tid & 1) * 16;    // two 16-wide halves
    const int b_n   = tid & 63;          // 0..63
    const int b_k0  = (tid >> 6) * 8;    // 4 groups of 8 k

    const int g  = lane >> 2;            // 0..7
    const int cq = lane & 3;             // 0..3

    float acc[2][4][4] = {};

    for (int k0 = 0; k0 < K; k0 += 32) {
#pragma unroll
        for (int i = 0; i < 4; i++) {
            float4 v = *(const float4*)&A[(size_t)(m0 + a_row) * K + k0 + a_k0 + i * 4];
            As[a_row][a_k0 + i * 4 + 0] = f2tf32(v.x);
            As[a_row][a_k0 + i * 4 + 1] = f2tf32(v.y);
            As[a_row][a_k0 + i * 4 + 2] = f2tf32(v.z);
            As[a_row][a_k0 + i * 4 + 3] = f2tf32(v.w);
        }
#pragma unroll
        for (int i = 0; i < 8; i++) {
            float v = B[(size_t)(k0 + b_k0 + i) * N + n0 + b_n];
            Bs[b_n][b_k0 + i] = f2tf32(v);
        }
        __syncthreads();

#pragma unroll
        for (int kk = 0; kk < 32; kk += 8) {
            uint32_t af[2][4], bf[4][2];
#pragma unroll
            for (int im = 0; im < 2; im++) {
                int mb = wm + im * 16;
                af[im][0] = As[mb + g    ][kk + cq];
                af[im][1] = As[mb + g + 8][kk + cq];
                af[im][2] = As[mb + g    ][kk + cq + 4];
                af[im][3] = As[mb + g + 8][kk + cq + 4];
            }
#pragma unroll
            for (int in = 0; in < 4; in++) {
                int nb = wn + in * 8;
                bf[in][0] = Bs[nb + g][kk + cq];
                bf[in][1] = Bs[nb + g][kk + cq + 4];
            }
#pragma unroll
            for (int im = 0; im < 2; im++)
#pragma unroll
                for (int in = 0; in < 4; in++) {
                    asm volatile(
                        "mma.sync.aligned.m16n8k8.row.col.f32.tf32.tf32.f32 "
                        "{%0,%1,%2,%3}, {%4,%5,%6,%7}, {%8,%9}, {%0,%1,%2,%3};"
                        : "+f"(acc[im][in][0]), "+f"(acc[im][in][1]),
                          "+f"(acc[im][in][2]), "+f"(acc[im][in][3])
                        : "r"(af[im][0]), "r"(af[im][1]), "r"(af[im][2]), "r"(af[im][3]),
                          "r"(bf[in][0]), "r"(bf[in][1]));
                }
        }
        __syncthreads();
    }

#pragma unroll
    for (int im = 0; im < 2; im++)
#pragma unroll
        for (int in = 0; in < 4; in++) {
            int cbase = n0 + wn + in * 8 + 2 * cq;
#pragma unroll
            for (int half = 0; half < 2; half++) {
                int m = m0 + wm + im * 16 + g + half * 8;
#pragma unroll
                for (int jj = 0; jj < 2; jj++) {
                    int n = cbase + jj;
                    float v = acc[im][in][half * 2 + jj];
                    if (EPI == 2) v = fmaxf(v + bias[n], 0.0f);
                    if (EPI == 3) v = gelu_exact((v + bias[n]) * gam[n] + bet[n]);
                    if (EPI == 4) v = res[(size_t)m * N + n] + (v + bias[n]) * gam[n] + bet[n];
                    C[(size_t)m * N + n] = v;
                }
            }
        }
}

// =================================================================
// fp32 GEMM (graph path — unchanged, bit-identical results)
// =================================================================
#define GBM 128
#define GBN 64
#define GBK 16

template <int EPI>
__global__ __launch_bounds__(256) void gemm128_kernel(
    const float* __restrict__ A, const float* __restrict__ B, float* __restrict__ C,
    int M, int N, int K,
    const float* __restrict__ bias, const float* __restrict__ gam,
    const float* __restrict__ bet,  const float* __restrict__ res)
{
    __shared__ float As[2][GBK][GBM];
    __shared__ float Bs[2][GBK][GBN];
    const int tid = threadIdx.x;
    const int tx = tid & 15, ty = tid >> 4;
    const int m0 = blockIdx.y * GBM, n0 = blockIdx.x * GBN;
    const int a_m = tid >> 1, a_k = (tid & 1) * 8;
    const int b_k = tid >> 4, b_n = (tid & 15) * 4;

    const float* Ap = A + (size_t)(m0 + a_m) * K + a_k;
    const float* Bp = B + (size_t)b_k * N + n0 + b_n;

    float4 a0 = *(const float4*)Ap;
    float4 a1 = *(const float4*)(Ap + 4);
    float4 bv = *(const float4*)Bp;

    As[0][a_k + 0][a_m] = a0.x; As[0][a_k + 1][a_m] = a0.y;
    As[0][a_k + 2][a_m] = a0.z; As[0][a_k + 3][a_m] = a0.w;
    As[0][a_k + 4][a_m] = a1.x; As[0][a_k + 5][a_m] = a1.y;
    As[0][a_k + 6][a_m] = a1.z; As[0][a_k + 7][a_m] = a1.w;
    *(float4*)&Bs[0][b_k][b_n] = bv;
    __syncthreads();

    float acc[8][4] = {};
    int buf = 0;
    for (int k0 = GBK; ; k0 += GBK) {
        const bool more = (k0 < K);
        if (more) {
            a0 = *(const float4*)(Ap + k0);
            a1 = *(const float4*)(Ap + k0 + 4);
            bv = *(const float4*)(Bp + (size_t)k0 * N);
        }
#pragma unroll
        for (int k = 0; k < GBK; k++) {
            float ar[8], br[4];
            *(float4*)&ar[0] = *(float4*)&As[buf][k][ty * 8];
            *(float4*)&ar[4] = *(float4*)&As[buf][k][ty * 8 + 4];
            *(float4*)&br[0] = *(float4*)&Bs[buf][k][tx * 4];
#pragma unroll
            for (int i = 0; i < 8; i++)
#pragma unroll
                for (int j = 0; j < 4; j++) acc[i][j] = fmaf(ar[i], br[j], acc[i][j]);
        }
        if (!more) break;
        const int nb = buf ^ 1;
        As[nb][a_k + 0][a_m] = a0.x; As[nb][a_k + 1][a_m] = a0.y;
        As[nb][a_k + 2][a_m] = a0.z; As[nb][a_k + 3][a_m] = a0.w;
        As[nb][a_k + 4][a_m] = a1.x; As[nb][a_k + 5][a_m] = a1.y;
        As[nb][a_k + 6][a_m] = a1.z; As[nb][a_k + 7][a_m] = a1.w;
        *(float4*)&Bs[nb][b_k][b_n] = bv;
        __syncthreads();
        buf = nb;
    }

#pragma unroll
    for (int i = 0; i < 8; i++) {
        int m = m0 + ty * 8 + i;
#pragma unroll
        for (int j = 0; j < 4; j++) {
            int n = n0 + tx * 4 + j;
            float v = acc[i][j];
            if (EPI == 1) v += bias[n];
            if (EPI == 2) v = fmaxf(v + bias[n], 0.0f);
            if (EPI == 3) v = gelu_exact((v + bias[n]) * gam[n] + bet[n]);
            if (EPI == 4) v = res[(size_t)m * N + n] + (v + bias[n]) * gam[n] + bet[n];
            C[(size_t)m * N + n] = v;
        }
    }
}

// =================================================================
// stem: implicit im2col GEMM (unchanged)
// =================================================================
__global__ __launch_bounds__(256) void stem_gemm_kernel(
    const float* __restrict__ X, const float* __restrict__ Bw, float* __restrict__ C,
    const float* __restrict__ bias, const float* __restrict__ pos)
{
    const int Kd = 768, Nd = 192;
    __shared__ float As[2][GBK][GBM];
    __shared__ float Bs[2][GBK][GBN];
    const int tid = threadIdx.x;
    const int tx = tid & 15, ty = tid >> 4;
    const int m0 = blockIdx.y * GBM, n0 = blockIdx.x * GBN;
    const int a_m = tid >> 1, a_k = (tid & 1) * 8;
    const int b_k = tid >> 4, b_n = (tid & 15) * 4;

    const int m = m0 + a_m;
    const int bimg = m / NNODE;
    const int nsp = m % NNODE;
    const int py = nsp / HGRID, px = nsp % HGRID;
    const float* xbase = X + (size_t)bimg * 3 * IMGSZ * IMGSZ
                           + (size_t)(py * PATCH) * IMGSZ + px * PATCH;
    const float* Bp = Bw + (size_t)b_k * Nd + n0 + b_n;

    auto aptr = [&](int k) -> const float* {
        int ci = k >> 8, ky = (k >> 4) & 15, kx = k & 15;
        return xbase + (size_t)ci * IMGSZ * IMGSZ + ky * IMGSZ + kx;
    };

    const float* xr = aptr(a_k);
    float4 a0 = *(const float4*)xr;
    float4 a1 = *(const float4*)(xr + 4);
    float4 bv = *(const float4*)Bp;

    As[0][a_k + 0][a_m] = a0.x; As[0][a_k + 1][a_m] = a0.y;
    As[0][a_k + 2][a_m] = a0.z; As[0][a_k + 3][a_m] = a0.w;
    As[0][a_k + 4][a_m] = a1.x; As[0][a_k + 5][a_m] = a1.y;
    As[0][a_k + 6][a_m] = a1.z; As[0][a_k + 7][a_m] = a1.w;
    *(float4*)&Bs[0][b_k][b_n] = bv;
    __syncthreads();

    float acc[8][4] = {};
    int buf = 0;
    for (int k0 = GBK; ; k0 += GBK) {
        const bool more = (k0 < Kd);
        if (more) {
            const float* xn = aptr(k0 + a_k);
            a0 = *(const float4*)xn;
            a1 = *(const float4*)(xn + 4);
            bv = *(const float4*)(Bp + (size_t)k0 * Nd);
        }
#pragma unroll
        for (int k = 0; k < GBK; k++) {
            float ar[8], br[4];
            *(float4*)&ar[0] = *(float4*)&As[buf][k][ty * 8];
            *(float4*)&ar[4] = *(float4*)&As[buf][k][ty * 8 + 4];
            *(float4*)&br[0] = *(float4*)&Bs[buf][k][tx * 4];
#pragma unroll
            for (int i = 0; i < 8; i++)
#pragma unroll
                for (int j = 0; j < 4; j++) acc[i][j] = fmaf(ar[i], br[j], acc[i][j]);
        }
        if (!more) break;
        const int nb = buf ^ 1;
        As[nb][a_k + 0][a_m] = a0.x; As[nb][a_k + 1][a_m] = a0.y;
        As[nb][a_k + 2][a_m] = a0.z; As[nb][a_k + 3][a_m] = a0.w;
        As[nb][a_k + 4][a_m] = a1.x; As[nb][a_k + 5][a_m] = a1.y;
        As[nb][a_k + 6][a_m] = a1.z; As[nb][a_k + 7][a_m] = a1.w;
        *(float4*)&Bs[nb][b_k][b_n] = bv;
        __syncthreads();
        buf = nb;
    }

#pragma unroll
    for (int i = 0; i < 8; i++) {
        int mm = m0 + ty * 8 + i;
        int sp = mm % NNODE;
#pragma unroll
        for (int j = 0; j < 4; j++) {
            int n = n0 + tx * 4 + j;
            C[(size_t)mm * CH + n] = acc[i][j] + bias[n] + pos[n * NNODE + sp];
        }
    }
}

// =================================================================
// gram (unchanged, bit-identical)
// =================================================================
__global__ __launch_bounds__(128) void gram2_kernel(
    const float* __restrict__ nf, const float* __restrict__ sq, float* __restrict__ d2)
{
    const int b = blockIdx.z;
    const float* Ab = nf + (size_t)b * NNODE * CH;
    __shared__ float As[2][GBK][64];
    __shared__ float Bs[2][GBK][64];
    const int tid = threadIdx.x;
    const int tx = tid & 15, ty = tid >> 4;
    const int r0 = blockIdx.y * 64, c0 = blockIdx.x * 64;
    const int l_m = tid >> 1, l_k = (tid & 1) * 8;

    const float* Apt = Ab + (size_t)(r0 + l_m) * CH + l_k;
    const float* Bpt = Ab + (size_t)(c0 + l_m) * CH + l_k;

    float4 a0 = *(const float4*)Apt;
    float4 a1 = *(const float4*)(Apt + 4);
    float4 c0v = *(const float4*)Bpt;
    float4 c1v = *(const float4*)(Bpt + 4);

    As[0][l_k + 0][l_m] = a0.x; As[0][l_k + 1][l_m] = a0.y;
    As[0][l_k + 2][l_m] = a0.z; As[0][l_k + 3][l_m] = a0.w;
    As[0][l_k + 4][l_m] = a1.x; As[0][l_k + 5][l_m] = a1.y;
    As[0][l_k + 6][l_m] = a1.z; As[0][l_k + 7][l_m] = a1.w;
    Bs[0][l_k + 0][l_m] = c0v.x; Bs[0][l_k + 1][l_m] = c0v.y;
    Bs[0][l_k + 2][l_m] = c0v.z; Bs[0][l_k + 3][l_m] = c0v.w;
    Bs[0][l_k + 4][l_m] = c1v.x; Bs[0][l_k + 5][l_m] = c1v.y;
    Bs[0][l_k + 6][l_m] = c1v.z; Bs[0][l_k + 7][l_m] = c1v.w;
    __syncthreads();

    float acc[8][4] = {};
    int buf = 0;
    for (int k0 = GBK; ; k0 += GBK) {
        const bool more = (k0 < CH);
        if (more) {
            a0  = *(const float4*)(Apt + k0);
            a1  = *(const float4*)(Apt + k0 + 4);
            c0v = *(const float4*)(Bpt + k0);
            c1v = *(const float4*)(Bpt + k0 + 4);
        }
#pragma unroll
        for (int k = 0; k < GBK; k++) {
            float ar[8], br[4];
            *(float4*)&ar[0] = *(float4*)&As[buf][k][ty * 8];
            *(float4*)&ar[4] = *(float4*)&As[buf][k][ty * 8 + 4];
            *(float4*)&br[0] = *(float4*)&Bs[buf][k][tx * 4];
#pragma unroll
            for (int i = 0; i < 8; i++)
#pragma unroll
                for (int j = 0; j < 4; j++) acc[i][j] = fmaf(ar[i], br[j], acc[i][j]);
        }
        if (!more) break;
        const int nb = buf ^ 1;
        As[nb][l_k + 0][l_m] = a0.x; As[nb][l_k + 1][l_m] = a0.y;
        As[nb][l_k + 2][l_m] = a0.z; As[nb][l_k + 3][l_m] = a0.w;
        As[nb][l_k + 4][l_m] = a1.x; As[nb][l_k + 5][l_m] = a1.y;
        As[nb][l_k + 6][l_m] = a1.z; As[nb][l_k + 7][l_m] = a1.w;
        Bs[nb][l_k + 0][l_m] = c0v.x; Bs[nb][l_k + 1][l_m] = c0v.y;
        Bs[nb][l_k + 2][l_m] = c0v.z; Bs[nb][l_k + 3][l_m] = c0v.w;
        Bs[nb][l_k + 4][l_m] = c1v.x; Bs[nb][l_k + 5][l_m] = c1v.y;
        Bs[nb][l_k + 6][l_m] = c1v.z; Bs[nb][l_k + 7][l_m] = c1v.w;
        __syncthreads();
        buf = nb;
    }

#pragma unroll
    for (int i = 0; i < 8; i++) {
        int r = r0 + ty * 8 + i;
#pragma unroll
        for (int j = 0; j < 4; j++) {
            int c = c0 + tx * 4 + j;
            float v = sq[b * NNODE + c] - 2.0f * acc[i][j];
            if (r == c) v = 3.0e38f;
            d2[((size_t)b * NNODE + r) * NNODE + c] = v;
        }
    }
}

// ---------------- small-M SGEMM for pred head (M=64) ----------------
#define BM 64
#define BNT 64
#define BKT 16
template <int EPI>
__global__ __launch_bounds__(256) void sgemm_kernel(
    const float* __restrict__ A, const float* __restrict__ B, float* __restrict__ C,
    int M, int N, int K,
    const float* __restrict__ bias, const float* __restrict__ gam,
    const float* __restrict__ bet,  const float* __restrict__ res)
{
    __shared__ float As[BKT][BM];
    __shared__ float Bs[BKT][BNT];
    const int tid = threadIdx.x;
    const int tx = tid & 15, ty = tid >> 4;
    const int m0 = blockIdx.y * BM, n0 = blockIdx.x * BNT;
    const int a_m = tid >> 2, a_k = (tid & 3) * 4;
    const int b_k = tid >> 4, b_n = (tid & 15) * 4;

    float acc[4][4] = {};
    for (int k0 = 0; k0 < K; k0 += BKT) {
        float4 av = *(const float4*)&A[(size_t)(m0 + a_m) * K + k0 + a_k];
        As[a_k + 0][a_m] = av.x; As[a_k + 1][a_m] = av.y;
        As[a_k + 2][a_m] = av.z; As[a_k + 3][a_m] = av.w;
        float4 bv = *(const float4*)&B[(size_t)(k0 + b_k) * N + n0 + b_n];
        *(float4*)&Bs[b_k][b_n] = bv;
        __syncthreads();
#pragma unroll
        for (int k = 0; k < BKT; k++) {
            float ar[4], br[4];
#pragma unroll
            for (int i = 0; i < 4; i++) ar[i] = As[k][ty * 4 + i];
#pragma unroll
            for (int j = 0; j < 4; j++) br[j] = Bs[k][tx * 4 + j];
#pragma unroll
            for (int i = 0; i < 4; i++)
#pragma unroll
                for (int j = 0; j < 4; j++) acc[i][j] = fmaf(ar[i], br[j], acc[i][j]);
        }
        __syncthreads();
    }
#pragma unroll
    for (int i = 0; i < 4; i++) {
        int m = m0 + ty * 4 + i;
#pragma unroll
        for (int j = 0; j < 4; j++) {
            int n = n0 + tx * 4 + j;
            float v = acc[i][j];
            if (EPI == 1) v += bias[n];
            if (EPI == 2) v = fmaxf(v + bias[n], 0.0f);
            if (EPI == 3) v = gelu_exact((v + bias[n]) * gam[n] + bet[n]);
            if (EPI == 4) v = res[(size_t)m * N + n] + (v + bias[n]) * gam[n] + bet[n];
            C[(size_t)m * N + n] = v;
        }
    }
}

// ---------------- auxiliary kernels (unchanged) ----------------
__global__ void transpose_w_kernel(const float* __restrict__ w, float* __restrict__ wt) {
    int i = blockIdx.x * blockDim.x + threadIdx.x;
    if (i >= 192 * 768) return;
    int n = i / 768, k = i % 768;
    wt[k * 192 + n] = w[i];
}

__global__ void sq_kernel(const float* __restrict__ nf, float* __restrict__ sq) {
    int node = (blockIdx.x * blockDim.x + threadIdx.x) >> 5;
    int lane = threadIdx.x & 31;
    if (node >= BN) return;
    float s = 0.f;
#pragma unroll
    for (int j = 0; j < 6; j++) {
        float x = nf[(size_t)node * CH + lane + 32 * j];
        s = fmaf(x, x, s);
    }
#pragma unroll
    for (int off = 16; off; off >>= 1) s += __shfl_down_sync(0xffffffffu, s, off);
    if (lane == 0) sq[node] = s;
}

__global__ void topk_kernel(const float* __restrict__ d2, int* __restrict__ idx) {
    int row = (blockIdx.x * blockDim.x + threadIdx.x) >> 5;
    int lane = threadIdx.x & 31;
    if (row >= BN) return;
    const float* r = d2 + (size_t)row * NNODE;
    float v[18];
#pragma unroll
    for (int j = 0; j < 18; j++) v[j] = r[lane + 32 * j];
    int bimg = row / NNODE;
#pragma unroll
    for (int s = 0; s < 5; s++) {
        float bv = 3.4e38f; int bc = 1 << 30;
#pragma unroll
        for (int j = 0; j < 18; j++) {
            int c = lane + 32 * j;
            if (v[j] < bv) { bv = v[j]; bc = c; }
        }
#pragma unroll
        for (int off = 16; off; off >>= 1) {
            float ov = __shfl_down_sync(0xffffffffu, bv, off);
            int   oc = __shfl_down_sync(0xffffffffu, bc, off);
            if (ov < bv || (ov == bv && oc < bc)) { bv = ov; bc = oc; }
        }
        bc = __shfl_sync(0xffffffffu, bc, 0);
        if ((bc & 31) == lane) v[bc >> 5] = 3.4e38f;
        if (lane == 0) idx[row * KNN + s] = bimg * NNODE + bc;
    }
}

__global__ void edge_kernel(const float* __restrict__ P, const float* __restrict__ Q,
                            const int* __restrict__ idx,
                            const float* __restrict__ w2, const float* __restrict__ b2,
                            float* __restrict__ att, float* __restrict__ out)
{
    int e = (blockIdx.x * blockDim.x + threadIdx.x) >> 5;
    int lane = threadIdx.x & 31;
    if (e >= EDG) return;
    int dst = e / KNN;
    int src = idx[e];
    float s = 0.f;
#pragma unroll
    for (int j = 0; j < 6; j++) {
        int c = lane + 32 * j;
        float x = P[(size_t)src * CH + c] + Q[(size_t)dst * CH + c];
        x = fmaxf(x, 0.f);
        s = fmaf(x, w2[c], s);
    }
#pragma unroll
    for (int off = 16; off; off >>= 1) s += __shfl_down_sync(0xffffffffu, s, off);
    if (lane == 0) {
        float a = 1.0f / (1.0f + expf(-(s + b2[0])));
        att[e] = a;
        out[e] = a;
    }
}

__global__ void agg_kernel(const float* __restrict__ h, const int* __restrict__ idx,
                           const float* __restrict__ att, float* __restrict__ hm)
{
    int i = blockIdx.x;
    int c = threadIdx.x;
    float acc = h[(size_t)i * CH + c];
#pragma unroll
    for (int k = 0; k < KNN; k++) {
        int nb = idx[i * KNN + k];
        float a = att[i * KNN + k];
        acc = fmaf(a, h[(size_t)nb * CH + c], acc);
    }
    hm[(size_t)i * CH + c] = acc;
}

__global__ void pool_kernel(const float* __restrict__ t, float* __restrict__ g) {
    int b = blockIdx.x, c = threadIdx.x;
    float acc = 0.f;
    for (int n = 0; n < NNODE; n++) acc += t[((size_t)b * NNODE + n) * CH + c];
    g[b * CH + c] = acc * (1.0f / NNODE);
}

__global__ void pred_final_kernel(const float* __restrict__ p, const float* __restrict__ w2,
                                  const float* __restrict__ b2, float* __restrict__ out)
{
    int b = blockIdx.x, tid = threadIdx.x;
    float s = 0.f;
    for (int i = tid; i < PHID; i += 256) s = fmaf(p[(size_t)b * PHID + i], w2[i], s);
    __shared__ float red[256];
    red[tid] = s; __syncthreads();
    for (int st = 128; st; st >>= 1) { if (tid < st) red[tid] += red[tid + st]; __syncthreads(); }
    if (tid == 0) out[b] = red[0] + b2[0];
}

// ---------------- host launch ----------------
extern "C" void kernel_launch(void* const* d_in, const int* in_sizes, int n_in,
                              void* d_out, int out_size)
{
    const float* x        = (const float*)d_in[0];
    const float* stem_w   = (const float*)d_in[1];
    const float* stem_b   = (const float*)d_in[2];
    const float* pos      = (const float*)d_in[3];
    const float* att_w1   = (const float*)d_in[4];
    const float* att_b1   = (const float*)d_in[5];
    const float* att_w2   = (const float*)d_in[6];
    const float* att_b2   = (const float*)d_in[7];
    const float* gnn_w1   = (const float*)d_in[8];
    const float* gnn_b1   = (const float*)d_in[9];
    const float* gnn_w2   = (const float*)d_in[10];
    const float* gnn_b2   = (const float*)d_in[11];
    const float* ffn_w1   = (const float*)d_in[12];
    const float* ffn_b1   = (const float*)d_in[13];
    const float* ffn_g1   = (const float*)d_in[14];
    const float* ffn_be1  = (const float*)d_in[15];
    const float* ffn_w2   = (const float*)d_in[16];
    const float* ffn_b2   = (const float*)d_in[17];
    const float* ffn_g2   = (const float*)d_in[18];
    const float* ffn_be2  = (const float*)d_in[19];
    const float* pred_w1  = (const float*)d_in[20];
    const float* pred_b1  = (const float*)d_in[21];
    const float* pred_g   = (const float*)d_in[22];
    const float* pred_be  = (const float*)d_in[23];
    const float* pred_w2  = (const float*)d_in[24];
    const float* pred_b2  = (const float*)d_in[25];
    float* out = (float*)d_out;

    float *p_wt, *p_nf, *p_sq, *p_d2, *p_P, *p_Q, *p_att, *p_h, *p_hm, *p_u, *p_t, *p_g, *p_p;
    int* p_idx;
    cudaGetSymbolAddress((void**)&p_wt,  g_wt);
    cudaGetSymbolAddress((void**)&p_nf,  g_nf);
    cudaGetSymbolAddress((void**)&p_sq,  g_sq);
    cudaGetSymbolAddress((void**)&p_d2,  g_d2);
    cudaGetSymbolAddress((void**)&p_idx, g_idx);
    cudaGetSymbolAddress((void**)&p_P,   g_P);
    cudaGetSymbolAddress((void**)&p_Q,   g_Q);
    cudaGetSymbolAddress((void**)&p_att, g_att);
    cudaGetSymbolAddress((void**)&p_h,   g_h);
    cudaGetSymbolAddress((void**)&p_hm,  g_hm);
    cudaGetSymbolAddress((void**)&p_u,   g_u);
    cudaGetSymbolAddress((void**)&p_t,   g_t);
    cudaGetSymbolAddress((void**)&p_g,   g_g);
    cudaGetSymbolAddress((void**)&p_p,   g_p);

    transpose_w_kernel<<<(192 * 768 + 255) / 256, 256>>>(stem_w, p_wt);

    // ---- graph path (bit-identical fp32) ----
    stem_gemm_kernel<<<dim3(CH / GBN, BN / GBM), 256>>>(x, p_wt, p_nf, stem_b, pos);
    sq_kernel<<<(BN * 32 + 255) / 256, 256>>>(p_nf, p_sq);
    gram2_kernel<<<dim3(NNODE / 64, NNODE / 64, Bsz), 128>>>(p_nf, p_sq, p_d2);
    topk_kernel<<<(BN * 32 + 255) / 256, 256>>>(p_d2, p_idx);
    gemm128_kernel<0><<<dim3(CH / GBN, BN / GBM), 256>>>(p_nf, att_w1, p_P, BN, CH, CH,
                                                         nullptr, nullptr, nullptr, nullptr);
    gemm128_kernel<1><<<dim3(CH / GBN, BN / GBM), 256>>>(p_nf, att_w1 + 192 * 192, p_Q, BN, CH, CH,
                                                         att_b1, nullptr, nullptr, nullptr);
    edge_kernel<<<(EDG * 32 + 255) / 256, 256>>>(p_P, p_Q, p_idx, att_w2, att_b2, p_att, out);

    // ---- prediction path (tf32 tensor cores) ----
    agg_kernel<<<BN, CH>>>(p_nf, p_idx, p_att, p_hm);
    tf32gemm_kernel<2><<<dim3(CH / 64, BN / 128), 256>>>(p_hm, gnn_w1, p_h, BN, CH, CH,
                                                         gnn_b1, nullptr, nullptr, nullptr);
    agg_kernel<<<BN, CH>>>(p_h, p_idx, p_att, p_hm);
    tf32gemm_kernel<2><<<dim3(CH / 64, BN / 128), 256>>>(p_hm, gnn_w2, p_h, BN, CH, CH,
                                                         gnn_b2, nullptr, nullptr, nullptr);
    tf32gemm_kernel<3><<<dim3(HID / 64, BN / 128), 256>>>(p_h, ffn_w1, p_u, BN, HID, CH,
                                                          ffn_b1, ffn_g1, ffn_be1, nullptr);
    tf32gemm_kernel<4><<<dim3(CH / 64, BN / 128), 256>>>(p_u, ffn_w2, p_t, BN, CH, HID,
                                                         ffn_b2, ffn_g2, ffn_be2, p_h);

    pool_kernel<<<Bsz, CH>>>(p_t, p_g);
    sgemm_kernel<3><<<dim3(PHID / BNT, Bsz / BM), 256>>>(p_g, pred_w1, p_p, Bsz, PHID, CH,
                                                         pred_b1, pred_g, pred_be, nullptr);
    pred_final_kernel<<<Bsz, 256>>>(p_p, pred_w2, pred_b2, out + EDG);
}